// round 3
// baseline (speedup 1.0000x reference)
#include <cuda_runtime.h>
#include <math_constants.h>

#define BATCH 16
#define HEADS 8
#define SEQ   1024
#define DIM   64

#define QB 32          // q rows per block
#define KT 64          // k rows per tile
#define SQ_STRIDE  132
#define SKT_STRIDE 66
#define SV_STRIDE  132
#define SPS_STRIDE 66

#define SMEM_FLOATS (QB*SQ_STRIDE + 128*SKT_STRIDE + KT*SV_STRIDE + QB*SPS_STRIDE)
#define SMEM_BYTES  (SMEM_FLOATS * 4)

// scratch (no cudaMalloc allowed)
__device__ int g_i0[BATCH*SEQ];
__device__ int g_i1[BATCH*SEQ];
__device__ int g_list[BATCH*2*SEQ];
__device__ int g_cnt[BATCH*2];

__global__ void init_kernel() {
    int t = threadIdx.x;
    if (t < BATCH*2) g_cnt[t] = 0;
}

// One block per (b, s): exact IoU argmax (first-tie), pair selection, group compaction.
// All arithmetic replicates XLA fp32: each mul/add/sub/div single-rounded (no FMA fusion).
__global__ __launch_bounds__(256) void pairs_kernel(const float* __restrict__ centers) {
    int bs = blockIdx.x;
    int b = bs >> 10;
    int s = bs & 1023;
    const float4* cp = (const float4*)centers;
    float4 bb = cp[bs];
    // box = (cx - w/2, cy - h/2, cx + w/2, cy + h/2); centers = (cx, cy, h, w)
    float x1 = bb.x - 0.5f*bb.w;
    float y1 = bb.y - 0.5f*bb.z;
    float x2 = bb.x + 0.5f*bb.w;
    float y2 = bb.y + 0.5f*bb.z;
    float areas = __fmul_rn(__fsub_rn(x2,x1), __fsub_rn(y2,y1));

    float best = -CUDART_INF_F;
    int bidx = 0;
    for (int k = threadIdx.x; k < SEQ; k += 256) {
        float4 cb = cp[(b<<10)+k];
        float kx1 = cb.x - 0.5f*cb.w;
        float ky1 = cb.y - 0.5f*cb.z;
        float kx2 = cb.x + 0.5f*cb.w;
        float ky2 = cb.y + 0.5f*cb.z;
        float iw = __fsub_rn(fminf(x2,kx2), fmaxf(x1,kx1));
        float ih = __fsub_rn(fminf(y2,ky2), fmaxf(y1,ky1));
        float inter = __fmul_rn(iw, ih);                 // NOTE: no clamp, matches ref
        float ka = __fmul_rn(__fsub_rn(kx2,kx1), __fsub_rn(ky2,ky1));
        float uni = __fsub_rn(__fadd_rn(areas, ka), inter);
        float iou = __fdiv_rn(inter, uni);
        if (k == s) iou = __fsub_rn(iou, 1.0f);
        if (iou > best) { best = iou; bidx = k; }        // strict > keeps first index
    }
    __shared__ float sv[256];
    __shared__ int   si[256];
    int t = threadIdx.x;
    sv[t] = best; si[t] = bidx;
    __syncthreads();
    for (int off = 128; off > 0; off >>= 1) {
        if (t < off) {
            float v2 = sv[t+off]; int i2 = si[t+off];
            if (v2 > sv[t] || (v2 == sv[t] && i2 < si[t])) { sv[t] = v2; si[t] = i2; }
        }
        __syncthreads();
    }
    if (t == 0) {
        int p = si[0];
        float l1s = __fadd_rn(fabsf(__fsub_rn(x2,x1)), fabsf(__fsub_rn(y2,y1)));
        float4 pb = cp[(b<<10)+p];
        float px1 = pb.x - 0.5f*pb.w;
        float py1 = pb.y - 0.5f*pb.z;
        float px2 = pb.x + 0.5f*pb.w;
        float py2 = pb.y + 0.5f*pb.z;
        float l1p = __fadd_rn(fabsf(__fsub_rn(px2,px1)), fabsf(__fsub_rn(py2,py1)));
        bool keep0 = (l1s >= l1p);
        g_i0[bs] = keep0 ? s : p;
        g_i1[bs] = keep0 ? p : s;
        int g = keep0 ? 0 : 1;
        int slot = atomicAdd(&g_cnt[b*2 + g], 1);
        g_list[(b*2 + g)*SEQ + slot] = s;
    }
}

// Flash attention over gathered concatenated rows (effective head-dim 128).
// Block: (q-tile of 32 compacted rows, head h, batch b). 128 threads = 4 warps x 8 q-rows.
__global__ __launch_bounds__(128) void attn_kernel(
    const float* __restrict__ Q, const float* __restrict__ K,
    const float* __restrict__ V, float* __restrict__ out)
{
    int b = blockIdx.z, h = blockIdx.y;
    int g = h >> 2, hh = h & 3;
    int cnt = g_cnt[b*2 + g];
    int tile0 = blockIdx.x * QB;
    if (tile0 >= cnt) return;

    extern __shared__ float smem[];
    float* sQ  = smem;                       // [32][132]  Qcat rows (broadcast reads)
    float* sKT = sQ  + QB*SQ_STRIDE;         // [128][66]  Kcat transposed (c-major)
    float* sV  = sKT + 128*SKT_STRIDE;       // [64][132]  Vcat rows
    float* sPs = sV  + KT*SV_STRIDE;         // [32][66]   staged probabilities

    int t = threadIdx.x;
    int lane = t & 31, warp = t >> 5;
    const int* listp = g_list + (b*2 + g)*SEQ;
    const int* i0p = g_i0 + b*SEQ;
    const int* i1p = g_i1 + b*SEQ;
    size_t headbase = ((size_t)(b*HEADS + h)) * SEQ * DIM;

    // ---- load Q tile (gathered, concatenated) ----
    {
        int rr = t >> 2, chunk = t & 3;               // 32 rows x 4 col-chunks of 32
        int idx = tile0 + rr; if (idx >= cnt) idx = cnt - 1;
        int q = listp[idx];
        int src = (chunk < 2) ? i0p[q] : i1p[q];
        const float4* qp = (const float4*)(Q + headbase + (size_t)src*DIM + (size_t)((chunk & 1)*32));
        float* dst = sQ + rr*SQ_STRIDE + chunk*32;
        #pragma unroll
        for (int j = 0; j < 8; j++) {
            float4 v = qp[j];
            *(float4*)(dst + 4*j) = v;
        }
    }

    float2 s8[8];
    float4 oo[8];
    float mrow[8], lrow[8];
    #pragma unroll
    for (int r = 0; r < 8; r++) {
        oo[r] = make_float4(0.f,0.f,0.f,0.f);
        mrow[r] = -CUDART_INF_F;
        lrow[r] = 0.f;
    }

    for (int kt = 0; kt < SEQ/KT; kt++) {
        __syncthreads();   // prior PV done with sV/sKT; also covers initial sQ fill
        // ---- fill K^T and V tiles (gathered, concatenated) ----
        {
            int kk = t & 63, half = t >> 6;
            int k = kt*KT + kk;
            int src = half ? i1p[k] : i0p[k];
            const float4* kp = (const float4*)(K + headbase + (size_t)src*DIM);
            const float4* vp = (const float4*)(V + headbase + (size_t)src*DIM);
            int cbase = half*64;
            #pragma unroll
            for (int j = 0; j < 16; j++) {
                float4 v = kp[j];
                int c = cbase + 4*j;
                sKT[(c+0)*SKT_STRIDE + kk] = v.x;
                sKT[(c+1)*SKT_STRIDE + kk] = v.y;
                sKT[(c+2)*SKT_STRIDE + kk] = v.z;
                sKT[(c+3)*SKT_STRIDE + kk] = v.w;
            }
            #pragma unroll
            for (int j = 0; j < 16; j++) {
                float4 v = vp[j];
                *(float4*)(sV + kk*SV_STRIDE + cbase + 4*j) = v;
            }
        }
        __syncthreads();

        // ---- scores: 8 q-rows x 64 k (k' = 2*lane, 2*lane+1) ----
        #pragma unroll
        for (int r = 0; r < 8; r++) s8[r] = make_float2(0.f, 0.f);
        {
            const float* kcol = sKT + 2*lane;
            const float* qrow = sQ + warp*8*SQ_STRIDE;
            #pragma unroll 4
            for (int c = 0; c < 128; c += 2) {
                float2 ka = *(const float2*)(kcol + c*SKT_STRIDE);
                float2 kb = *(const float2*)(kcol + (c+1)*SKT_STRIDE);
                #pragma unroll
                for (int r = 0; r < 8; r++) {
                    float2 q = *(const float2*)(qrow + r*SQ_STRIDE + c);
                    s8[r].x += q.x*ka.x; s8[r].x += q.y*kb.x;
                    s8[r].y += q.x*ka.y; s8[r].y += q.y*kb.y;
                }
            }
        }

        // ---- online softmax + stage P ----
        #pragma unroll
        for (int r = 0; r < 8; r++) {
            float mt = fmaxf(s8[r].x, s8[r].y);
            #pragma unroll
            for (int off = 16; off > 0; off >>= 1)
                mt = fmaxf(mt, __shfl_xor_sync(0xffffffffu, mt, off));
            float mn = fmaxf(mrow[r], mt);
            float corr = __expf(mrow[r] - mn);     // -inf - finite -> exp = 0 (first tile)
            float p0 = __expf(s8[r].x - mn);
            float p1 = __expf(s8[r].y - mn);
            float lt = p0 + p1;
            #pragma unroll
            for (int off = 16; off > 0; off >>= 1)
                lt += __shfl_xor_sync(0xffffffffu, lt, off);
            lrow[r] = lrow[r]*corr + lt;
            mrow[r] = mn;
            oo[r].x *= corr; oo[r].y *= corr; oo[r].z *= corr; oo[r].w *= corr;
            *(float2*)(sPs + (warp*8 + r)*SPS_STRIDE + 2*lane) = make_float2(p0, p1);
        }
        __syncwarp();   // sPs rows are warp-private; warp-level ordering suffices

        // ---- PV: lane owns output cols 4*lane..4*lane+3 ----
        {
            const float* vbase = sV + 4*lane;
            const float* pbase = sPs + warp*8*SPS_STRIDE;
            #pragma unroll 4
            for (int k = 0; k < KT; k++) {
                float4 v = *(const float4*)(vbase + k*SV_STRIDE);
                #pragma unroll
                for (int r = 0; r < 8; r++) {
                    float p = pbase[r*SPS_STRIDE + k];   // broadcast
                    oo[r].x += p*v.x; oo[r].y += p*v.y;
                    oo[r].z += p*v.z; oo[r].w += p*v.w;
                }
            }
        }
    }

    // ---- epilogue: normalize, scale by 1/sqrt(2D), scatter to output row ----
    #pragma unroll
    for (int r = 0; r < 8; r++) {
        int idx = tile0 + warp*8 + r;
        if (idx < cnt) {
            int q = listp[idx];
            float inv = (1.0f / lrow[r]) * 0.08838834764831845f;  // 1/sqrt(128)
            float4 ov = make_float4(oo[r].x*inv, oo[r].y*inv, oo[r].z*inv, oo[r].w*inv);
            *(float4*)(out + ((size_t)(b*SEQ + q))*512 + hh*128 + 4*lane) = ov;
        }
    }
}

extern "C" void kernel_launch(void* const* d_in, const int* in_sizes, int n_in,
                              void* d_out, int out_size) {
    const float* Q = (const float*)d_in[0];
    const float* K = (const float*)d_in[1];
    const float* V = (const float*)d_in[2];
    const float* C = (const float*)d_in[3];
    float* out = (float*)d_out;

    // idempotent, host-side only (not replayed by the graph)
    cudaFuncSetAttribute(attn_kernel, cudaFuncAttributeMaxDynamicSharedMemorySize, SMEM_BYTES);

    init_kernel<<<1, 32>>>();
    pairs_kernel<<<BATCH*SEQ, 256>>>(C);
    attn_kernel<<<dim3(SEQ/QB, HEADS, BATCH), 128, SMEM_BYTES>>>(Q, K, V, out);
}

// round 6
// speedup vs baseline: 2.8982x; 2.8982x over previous
#include <cuda_runtime.h>
#include <cuda_bf16.h>
#include <cstdint>
#include <math_constants.h>

#define BATCH 16
#define HEADS 8
#define SEQ   1024
#define DIM   64

// ---------------- scratch ----------------
__device__ int g_i0[BATCH*SEQ];
__device__ int g_i1[BATCH*SEQ];
__device__ int g_list[BATCH*2*SEQ];
__device__ int g_cnt[BATCH*2];

// plain row-major bf16 blobs (hi/lo split)
// Q: per (b,h,qtile<8): 128 rows x 128 cols = 32768 B
// K,V: per (b,h,ktile<16): 64 rows x 128 cols = 16384 B
#define QBLOB_B(b,h,t)  ((size_t)((((b)*8+(h))*8)+(t)) * 32768)
#define KVBLOB_B(b,h,t) ((size_t)((((b)*8+(h))*16)+(t)) * 16384)
__device__ __align__(16) unsigned char gQh[BATCH*8*8*32768];
__device__ __align__(16) unsigned char gQl[BATCH*8*8*32768];
__device__ __align__(16) unsigned char gKh[BATCH*8*16*16384];
__device__ __align__(16) unsigned char gKl[BATCH*8*16*16384];
__device__ __align__(16) unsigned char gVh[BATCH*8*16*16384];
__device__ __align__(16) unsigned char gVl[BATCH*8*16*16384];

// ---------------- asm helpers (sm_80-level PTX only) ----------------
__device__ __forceinline__ uint32_t smem_u32(const void* p) {
    uint32_t a;
    asm("{ .reg .u64 t; cvta.to.shared.u64 t, %1; cvt.u32.u64 %0, t; }" : "=r"(a) : "l"(p));
    return a;
}
__device__ __forceinline__ void ldsm_x4(uint32_t* r, uint32_t addr) {
    asm volatile("ldmatrix.sync.aligned.m8n8.x4.shared.b16 {%0,%1,%2,%3}, [%4];"
        : "=r"(r[0]), "=r"(r[1]), "=r"(r[2]), "=r"(r[3]) : "r"(addr));
}
__device__ __forceinline__ void ldsm_x2(uint32_t* r, uint32_t addr) {
    asm volatile("ldmatrix.sync.aligned.m8n8.x2.shared.b16 {%0,%1}, [%2];"
        : "=r"(r[0]), "=r"(r[1]) : "r"(addr));
}
__device__ __forceinline__ void ldsm_x2t(uint32_t* r, uint32_t addr) {
    asm volatile("ldmatrix.sync.aligned.m8n8.x2.trans.shared.b16 {%0,%1}, [%2];"
        : "=r"(r[0]), "=r"(r[1]) : "r"(addr));
}
__device__ __forceinline__ void mma16816(float* d, const uint32_t* a, const uint32_t* b) {
    asm volatile("mma.sync.aligned.m16n8k16.row.col.f32.bf16.bf16.f32 "
        "{%0,%1,%2,%3}, {%4,%5,%6,%7}, {%8,%9}, {%0,%1,%2,%3};"
        : "+f"(d[0]), "+f"(d[1]), "+f"(d[2]), "+f"(d[3])
        : "r"(a[0]), "r"(a[1]), "r"(a[2]), "r"(a[3]), "r"(b[0]), "r"(b[1]));
}
#define CP16(dst, src) asm volatile("cp.async.cg.shared.global [%0], [%1], 16;" :: "r"(dst), "l"(src))
#define CP_COMMIT()    asm volatile("cp.async.commit_group;" ::: "memory")
#define CP_WAIT(n)     asm volatile("cp.async.wait_group %0;" :: "n"(n) : "memory")

__device__ __forceinline__ void split2(float a, float b, uint32_t& h, uint32_t& l) {
    __nv_bfloat162 hv = __floats2bfloat162_rn(a, b);
    float2 hf = __bfloat1622float2(hv);
    __nv_bfloat162 lv = __floats2bfloat162_rn(a - hf.x, b - hf.y);
    h = *reinterpret_cast<uint32_t*>(&hv);
    l = *reinterpret_cast<uint32_t*>(&lv);
}
__device__ __forceinline__ void pack8(float4 a, float4 b, uint4& uh, uint4& ul) {
    split2(a.x, a.y, uh.x, ul.x); split2(a.z, a.w, uh.y, ul.y);
    split2(b.x, b.y, uh.z, ul.z); split2(b.z, b.w, uh.w, ul.w);
}

// ---------------- init + pairs (exact, unchanged) ----------------
__global__ void init_kernel() {
    int t = threadIdx.x;
    if (t < BATCH*2) g_cnt[t] = 0;
}

__global__ __launch_bounds__(256) void pairs_kernel(const float* __restrict__ centers) {
    int bs = blockIdx.x;
    int b = bs >> 10, s = bs & 1023;
    const float4* cp = (const float4*)centers;
    float4 bb = cp[bs];
    float x1 = bb.x - 0.5f*bb.w, y1 = bb.y - 0.5f*bb.z;
    float x2 = bb.x + 0.5f*bb.w, y2 = bb.y + 0.5f*bb.z;
    float areas = __fmul_rn(__fsub_rn(x2,x1), __fsub_rn(y2,y1));
    float best = -CUDART_INF_F; int bidx = 0;
    for (int k = threadIdx.x; k < SEQ; k += 256) {
        float4 cb = cp[(b<<10)+k];
        float kx1 = cb.x - 0.5f*cb.w, ky1 = cb.y - 0.5f*cb.z;
        float kx2 = cb.x + 0.5f*cb.w, ky2 = cb.y + 0.5f*cb.z;
        float iw = __fsub_rn(fminf(x2,kx2), fmaxf(x1,kx1));
        float ih = __fsub_rn(fminf(y2,ky2), fmaxf(y1,ky1));
        float inter = __fmul_rn(iw, ih);
        float ka = __fmul_rn(__fsub_rn(kx2,kx1), __fsub_rn(ky2,ky1));
        float uni = __fsub_rn(__fadd_rn(areas, ka), inter);
        float iou = __fdiv_rn(inter, uni);
        if (k == s) iou = __fsub_rn(iou, 1.0f);
        if (iou > best) { best = iou; bidx = k; }
    }
    __shared__ float sv[256]; __shared__ int si[256];
    int t = threadIdx.x;
    sv[t] = best; si[t] = bidx;
    __syncthreads();
    for (int off = 128; off > 0; off >>= 1) {
        if (t < off) {
            float v2 = sv[t+off]; int i2 = si[t+off];
            if (v2 > sv[t] || (v2 == sv[t] && i2 < si[t])) { sv[t] = v2; si[t] = i2; }
        }
        __syncthreads();
    }
    if (t == 0) {
        int p = si[0];
        float l1s = __fadd_rn(fabsf(__fsub_rn(x2,x1)), fabsf(__fsub_rn(y2,y1)));
        float4 pb = cp[(b<<10)+p];
        float px1 = pb.x - 0.5f*pb.w, py1 = pb.y - 0.5f*pb.z;
        float px2 = pb.x + 0.5f*pb.w, py2 = pb.y + 0.5f*pb.z;
        float l1p = __fadd_rn(fabsf(__fsub_rn(px2,px1)), fabsf(__fsub_rn(py2,py1)));
        bool keep0 = (l1s >= l1p);
        g_i0[bs] = keep0 ? s : p;
        g_i1[bs] = keep0 ? p : s;
        int g = keep0 ? 0 : 1;
        int slot = atomicAdd(&g_cnt[b*2 + g], 1);
        g_list[(b*2 + g)*SEQ + slot] = s;
    }
}

// ---------------- builders: plain row-major bf16 hi/lo blobs ----------------
__global__ __launch_bounds__(128) void buildQ_kernel(const float* __restrict__ Q) {
    int t = threadIdx.x, tile = blockIdx.x, h = blockIdx.y, b = blockIdx.z;
    int g = h >> 2;
    int cnt = g_cnt[b*2 + g];
    if (tile*128 >= cnt) return;
    int idx = tile*128 + t; if (idx >= cnt) idx = cnt - 1;
    int q = g_list[(b*2+g)*SEQ + idx];
    int s0 = g_i0[b*SEQ+q], s1 = g_i1[b*SEQ+q];
    size_t hb = ((size_t)(b*HEADS + h)) * SEQ * DIM;
    const float4* p0 = (const float4*)(Q + hb + (size_t)s0*DIM);
    const float4* p1 = (const float4*)(Q + hb + (size_t)s1*DIM);
    uint4* dh = (uint4*)(gQh + QBLOB_B(b,h,tile)) + (size_t)t*16;
    uint4* dl = (uint4*)(gQl + QBLOB_B(b,h,tile)) + (size_t)t*16;
    #pragma unroll
    for (int c = 0; c < 16; c++) {
        const float4* sp = (c < 8) ? p0 : p1;
        int jj = (c & 7) * 2;
        float4 a = sp[jj], b2 = sp[jj+1];
        uint4 uh, ul; pack8(a, b2, uh, ul);
        dh[c] = uh; dl[c] = ul;
    }
}

__global__ __launch_bounds__(128) void buildKV_kernel(const float* __restrict__ K, const float* __restrict__ V) {
    int t = threadIdx.x, kt = blockIdx.x, h = blockIdx.y, b = blockIdx.z;
    int key = t >> 1, half = t & 1;
    int k = kt*64 + key;
    int src = half ? g_i1[b*SEQ+k] : g_i0[b*SEQ+k];
    size_t hb = ((size_t)(b*HEADS + h)) * SEQ * DIM;
    const float4* kp = (const float4*)(K + hb + (size_t)src*DIM);
    const float4* vp = (const float4*)(V + hb + (size_t)src*DIM);
    size_t roff = (size_t)key*16 + half*8;
    uint4* kh = (uint4*)(gKh + KVBLOB_B(b,h,kt)) + roff;
    uint4* kl = (uint4*)(gKl + KVBLOB_B(b,h,kt)) + roff;
    uint4* vh = (uint4*)(gVh + KVBLOB_B(b,h,kt)) + roff;
    uint4* vl = (uint4*)(gVl + KVBLOB_B(b,h,kt)) + roff;
    #pragma unroll
    for (int c = 0; c < 8; c++) {
        float4 a = kp[2*c], b2 = kp[2*c+1];
        uint4 uh, ul; pack8(a, b2, uh, ul);
        kh[c] = uh; kl[c] = ul;
        a = vp[2*c]; b2 = vp[2*c+1];
        pack8(a, b2, uh, ul);
        vh[c] = uh; vl[c] = ul;
    }
}

// ---------------- HMMA flash attention ----------------
// smem (bytes): Qh[128][136]bf16=34816, Ql=34816, then 2 KV buffers of
// {Kh,Kl,Vh,Vl} each 64x136 bf16 = 17408 -> 69632 per buffer. Total 208896.
#define QSTR   272
#define OQH    0
#define OQL    34816
#define OKV    69632
#define KVBUF  69632
#define OFF_KH 0
#define OFF_KL 17408
#define OFF_VH 34816
#define OFF_VL 52224
#define ASMEM  208896

__global__ __launch_bounds__(256, 1) void attn_kernel(float* __restrict__ out) {
    int tile = blockIdx.x, h = blockIdx.y, b = blockIdx.z;
    int g = h >> 2;
    int cnt = g_cnt[b*2 + g];
    if (tile*128 >= cnt) return;

    extern __shared__ char sm[];
    uint32_t sb = smem_u32(sm);
    int t = threadIdx.x, lane = t & 31, w = t >> 5;

    // ---- Q tile: gmem blobs -> smem (stride 272) ----
    {
        const uint4* qh = (const uint4*)(gQh + QBLOB_B(b,h,tile));
        const uint4* ql = (const uint4*)(gQl + QBLOB_B(b,h,tile));
        #pragma unroll
        for (int i = 0; i < 8; i++) {
            int idx = i*256 + t;
            int row = idx >> 4, c = idx & 15;
            *(uint4*)(sm + OQH + row*QSTR + c*16) = qh[idx];
            *(uint4*)(sm + OQL + row*QSTR + c*16) = ql[idx];
        }
    }

    // cp.async K/V tile issuer
    const size_t bh_kv = (size_t)(b*8 + h) * 16 * 16384;
    auto issue = [&](int kt, int buf) {
        size_t kb = bh_kv + (size_t)kt * 16384;
        const char* ph  = (const char*)(gKh + kb);
        const char* pl  = (const char*)(gKl + kb);
        const char* pvh = (const char*)(gVh + kb);
        const char* pvl = (const char*)(gVl + kb);
        uint32_t base = sb + OKV + buf*KVBUF;
        #pragma unroll
        for (int i = 0; i < 4; i++) {
            int idx = i*256 + t;
            int row = idx >> 4, c = idx & 15;
            uint32_t so = row*QSTR + c*16;
            int go = row*256 + c*16;
            CP16(base + OFF_KH + so, ph + go);
            CP16(base + OFF_KL + so, pl + go);
            CP16(base + OFF_VH + so, pvh + go);
            CP16(base + OFF_VL + so, pvl + go);
        }
    };

    issue(0, 0);
    CP_COMMIT();

    // per-lane ldmatrix offsets
    int l15 = lane & 15;
    uint32_t aH = sb + OQH + (w*16 + l15)*QSTR + ((lane >> 4) * 8) * 2;
    uint32_t aL = sb + OQL + (w*16 + l15)*QSTR + ((lane >> 4) * 8) * 2;
    uint32_t bOff = (l15 & 7)*QSTR + ((l15 >> 3) * 8) * 2;   // K rows
    uint32_t vOff = l15*QSTR;                                 // V rows (trans)

    float st[32], ot[64];
    #pragma unroll
    for (int i = 0; i < 64; i++) ot[i] = 0.f;
    float mref0 = 0.f, mref1 = 0.f, lr0 = 0.f, lr1 = 0.f;
    int buf = 0;

    for (int kt = 0; kt < 16; kt++) {
        if (kt < 15) { issue(kt+1, buf ^ 1); CP_COMMIT(); CP_WAIT(1); }
        else         { CP_WAIT(0); }
        __syncthreads();

        uint32_t kbH = sb + OKV + buf*KVBUF + OFF_KH + bOff;
        uint32_t kbL = sb + OKV + buf*KVBUF + OFF_KL + bOff;
        uint32_t vbH = sb + OKV + buf*KVBUF + OFF_VH + vOff;
        uint32_t vbL = sb + OKV + buf*KVBUF + OFF_VL + vOff;

        // ---- QK: S = QhKh + QhKl + QlKh ----
        #pragma unroll
        for (int i = 0; i < 32; i++) st[i] = 0.f;
        #pragma unroll
        for (int ks = 0; ks < 8; ks++) {
            uint32_t ah[4], al[4];
            ldsm_x4(ah, aH + ks*32);
            ldsm_x4(al, aL + ks*32);
            #pragma unroll
            for (int nt = 0; nt < 8; nt++) {
                uint32_t bh[2], bl[2];
                ldsm_x2(bh, kbH + nt*8*QSTR + ks*32);
                ldsm_x2(bl, kbL + nt*8*QSTR + ks*32);
                mma16816(st + nt*4, ah, bh);
                mma16816(st + nt*4, ah, bl);
                mma16816(st + nt*4, al, bh);
            }
        }

        // ---- softmax (fixed reference from tile 0) ----
        if (kt == 0) {
            float m0 = -CUDART_INF_F, m1 = -CUDART_INF_F;
            #pragma unroll
            for (int nt = 0; nt < 8; nt++) {
                m0 = fmaxf(m0, fmaxf(st[nt*4],   st[nt*4+1]));
                m1 = fmaxf(m1, fmaxf(st[nt*4+2], st[nt*4+3]));
            }
            m0 = fmaxf(m0, __shfl_xor_sync(0xffffffffu, m0, 1));
            m0 = fmaxf(m0, __shfl_xor_sync(0xffffffffu, m0, 2));
            m1 = fmaxf(m1, __shfl_xor_sync(0xffffffffu, m1, 1));
            m1 = fmaxf(m1, __shfl_xor_sync(0xffffffffu, m1, 2));
            mref0 = m0; mref1 = m1;
        }
        uint32_t pph0[8], pph1[8], ppl0[8], ppl1[8];
        #pragma unroll
        for (int nt = 0; nt < 8; nt++) {
            float p00 = __expf(st[nt*4]   - mref0);
            float p01 = __expf(st[nt*4+1] - mref0);
            float p10 = __expf(st[nt*4+2] - mref1);
            float p11 = __expf(st[nt*4+3] - mref1);
            lr0 += p00 + p01;
            lr1 += p10 + p11;
            split2(p00, p01, pph0[nt], ppl0[nt]);
            split2(p10, p11, pph1[nt], ppl1[nt]);
        }

        // ---- PV: O += PhVh + PhVl + PlVh ----
        #pragma unroll
        for (int tt = 0; tt < 4; tt++) {
            uint32_t aPh[4] = { pph0[2*tt], pph1[2*tt], pph0[2*tt+1], pph1[2*tt+1] };
            uint32_t aPl[4] = { ppl0[2*tt], ppl1[2*tt], ppl0[2*tt+1], ppl1[2*tt+1] };
            #pragma unroll
            for (int nt = 0; nt < 16; nt++) {
                uint32_t vh[2], vl[2];
                ldsm_x2t(vh, vbH + tt*16*QSTR + nt*16);
                ldsm_x2t(vl, vbL + tt*16*QSTR + nt*16);
                mma16816(ot + nt*4, aPh, vh);
                mma16816(ot + nt*4, aPh, vl);
                mma16816(ot + nt*4, aPl, vh);
            }
        }
        __syncthreads();
        buf ^= 1;
    }

    // ---- epilogue ----
    lr0 += __shfl_xor_sync(0xffffffffu, lr0, 1);
    lr0 += __shfl_xor_sync(0xffffffffu, lr0, 2);
    lr1 += __shfl_xor_sync(0xffffffffu, lr1, 1);
    lr1 += __shfl_xor_sync(0xffffffffu, lr1, 2);
    float inv0 = 0.08838834764831845f / lr0;   // 1/sqrt(2D)
    float inv1 = 0.08838834764831845f / lr1;

    const int* listp = g_list + (b*2+g)*SEQ;
    int r0 = tile*128 + w*16 + (lane >> 2);
    int colb = (lane & 3) * 2;
    if (r0 < cnt) {
        int q = listp[r0];
        float* op = out + ((size_t)(b*SEQ + q))*512 + (h & 3)*128;
        #pragma unroll
        for (int nt = 0; nt < 16; nt++)
            *(float2*)(op + nt*8 + colb) = make_float2(ot[nt*4]*inv0, ot[nt*4+1]*inv0);
    }
    int r1 = r0 + 8;
    if (r1 < cnt) {
        int q = listp[r1];
        float* op = out + ((size_t)(b*SEQ + q))*512 + (h & 3)*128;
        #pragma unroll
        for (int nt = 0; nt < 16; nt++)
            *(float2*)(op + nt*8 + colb) = make_float2(ot[nt*4+2]*inv1, ot[nt*4+3]*inv1);
    }
}

// ---------------- launch ----------------
extern "C" void kernel_launch(void* const* d_in, const int* in_sizes, int n_in,
                              void* d_out, int out_size) {
    const float* Q = (const float*)d_in[0];
    const float* K = (const float*)d_in[1];
    const float* V = (const float*)d_in[2];
    const float* C = (const float*)d_in[3];
    float* out = (float*)d_out;

    cudaFuncSetAttribute(attn_kernel, cudaFuncAttributeMaxDynamicSharedMemorySize, ASMEM);

    init_kernel<<<1, 32>>>();
    pairs_kernel<<<BATCH*SEQ, 256>>>(C);
    buildQ_kernel<<<dim3(8, HEADS, BATCH), 128>>>(Q);
    buildKV_kernel<<<dim3(16, HEADS, BATCH), 128>>>(K, V);
    attn_kernel<<<dim3(8, HEADS, BATCH), 256, ASMEM>>>(out);
}

// round 7
// speedup vs baseline: 3.7298x; 1.2869x over previous
#include <cuda_runtime.h>
#include <cuda_bf16.h>
#include <cstdint>
#include <math_constants.h>

#define BATCH 16
#define HEADS 8
#define SEQ   1024
#define DIM   64

// ---------------- scratch ----------------
__device__ int g_i0[BATCH*SEQ];
__device__ int g_i1[BATCH*SEQ];
__device__ int g_list[BATCH*2*SEQ];
__device__ int g_cnt[BATCH*2];

// Flat bf16 hi/lo arrays, same [b,h,s,d] layout as inputs. 16 MB each.
#define NELEM (BATCH*HEADS*SEQ*DIM)
__device__ __align__(16) unsigned char gQh[NELEM*2];
__device__ __align__(16) unsigned char gQl[NELEM*2];
__device__ __align__(16) unsigned char gKh[NELEM*2];
__device__ __align__(16) unsigned char gKl[NELEM*2];
__device__ __align__(16) unsigned char gVh[NELEM*2];
__device__ __align__(16) unsigned char gVl[NELEM*2];

// ---------------- asm helpers (sm_80-level PTX only) ----------------
__device__ __forceinline__ uint32_t smem_u32(const void* p) {
    uint32_t a;
    asm("{ .reg .u64 t; cvta.to.shared.u64 t, %1; cvt.u32.u64 %0, t; }" : "=r"(a) : "l"(p));
    return a;
}
__device__ __forceinline__ void ldsm_x4(uint32_t* r, uint32_t addr) {
    asm volatile("ldmatrix.sync.aligned.m8n8.x4.shared.b16 {%0,%1,%2,%3}, [%4];"
        : "=r"(r[0]), "=r"(r[1]), "=r"(r[2]), "=r"(r[3]) : "r"(addr));
}
__device__ __forceinline__ void ldsm_x2(uint32_t* r, uint32_t addr) {
    asm volatile("ldmatrix.sync.aligned.m8n8.x2.shared.b16 {%0,%1}, [%2];"
        : "=r"(r[0]), "=r"(r[1]) : "r"(addr));
}
__device__ __forceinline__ void ldsm_x2t(uint32_t* r, uint32_t addr) {
    asm volatile("ldmatrix.sync.aligned.m8n8.x2.trans.shared.b16 {%0,%1}, [%2];"
        : "=r"(r[0]), "=r"(r[1]) : "r"(addr));
}
__device__ __forceinline__ void mma16816(float* d, const uint32_t* a, const uint32_t* b) {
    asm volatile("mma.sync.aligned.m16n8k16.row.col.f32.bf16.bf16.f32 "
        "{%0,%1,%2,%3}, {%4,%5,%6,%7}, {%8,%9}, {%0,%1,%2,%3};"
        : "+f"(d[0]), "+f"(d[1]), "+f"(d[2]), "+f"(d[3])
        : "r"(a[0]), "r"(a[1]), "r"(a[2]), "r"(a[3]), "r"(b[0]), "r"(b[1]));
}
#define CP16(dst, src) asm volatile("cp.async.cg.shared.global [%0], [%1], 16;" :: "r"(dst), "l"(src))
#define CP_COMMIT()    asm volatile("cp.async.commit_group;" ::: "memory")
#define CP_WAIT(n)     asm volatile("cp.async.wait_group %0;" :: "n"(n) : "memory")

__device__ __forceinline__ void split2(float a, float b, uint32_t& h, uint32_t& l) {
    __nv_bfloat162 hv = __floats2bfloat162_rn(a, b);
    float2 hf = __bfloat1622float2(hv);
    __nv_bfloat162 lv = __floats2bfloat162_rn(a - hf.x, b - hf.y);
    h = *reinterpret_cast<uint32_t*>(&hv);
    l = *reinterpret_cast<uint32_t*>(&lv);
}

// ---------------- init + pairs (exact, unchanged) ----------------
__global__ void init_kernel() {
    int t = threadIdx.x;
    if (t < BATCH*2) g_cnt[t] = 0;
}

__global__ __launch_bounds__(256) void pairs_kernel(const float* __restrict__ centers) {
    int bs = blockIdx.x;
    int b = bs >> 10, s = bs & 1023;
    const float4* cp = (const float4*)centers;
    float4 bb = cp[bs];
    float x1 = bb.x - 0.5f*bb.w, y1 = bb.y - 0.5f*bb.z;
    float x2 = bb.x + 0.5f*bb.w, y2 = bb.y + 0.5f*bb.z;
    float areas = __fmul_rn(__fsub_rn(x2,x1), __fsub_rn(y2,y1));
    float best = -CUDART_INF_F; int bidx = 0;
    for (int k = threadIdx.x; k < SEQ; k += 256) {
        float4 cb = cp[(b<<10)+k];
        float kx1 = cb.x - 0.5f*cb.w, ky1 = cb.y - 0.5f*cb.z;
        float kx2 = cb.x + 0.5f*cb.w, ky2 = cb.y + 0.5f*cb.z;
        float iw = __fsub_rn(fminf(x2,kx2), fmaxf(x1,kx1));
        float ih = __fsub_rn(fminf(y2,ky2), fmaxf(y1,ky1));
        float inter = __fmul_rn(iw, ih);
        float ka = __fmul_rn(__fsub_rn(kx2,kx1), __fsub_rn(ky2,ky1));
        float uni = __fsub_rn(__fadd_rn(areas, ka), inter);
        float iou = __fdiv_rn(inter, uni);
        if (k == s) iou = __fsub_rn(iou, 1.0f);
        if (iou > best) { best = iou; bidx = k; }
    }
    __shared__ float sv[256]; __shared__ int si[256];
    int t = threadIdx.x;
    sv[t] = best; si[t] = bidx;
    __syncthreads();
    for (int off = 128; off > 0; off >>= 1) {
        if (t < off) {
            float v2 = sv[t+off]; int i2 = si[t+off];
            if (v2 > sv[t] || (v2 == sv[t] && i2 < si[t])) { sv[t] = v2; si[t] = i2; }
        }
        __syncthreads();
    }
    if (t == 0) {
        int p = si[0];
        float l1s = __fadd_rn(fabsf(__fsub_rn(x2,x1)), fabsf(__fsub_rn(y2,y1)));
        float4 pb = cp[(b<<10)+p];
        float px1 = pb.x - 0.5f*pb.w, py1 = pb.y - 0.5f*pb.z;
        float px2 = pb.x + 0.5f*pb.w, py2 = pb.y + 0.5f*pb.z;
        float l1p = __fadd_rn(fabsf(__fsub_rn(px2,px1)), fabsf(__fsub_rn(py2,py1)));
        bool keep0 = (l1s >= l1p);
        g_i0[bs] = keep0 ? s : p;
        g_i1[bs] = keep0 ? p : s;
        int g = keep0 ? 0 : 1;
        int slot = atomicAdd(&g_cnt[b*2 + g], 1);
        g_list[(b*2 + g)*SEQ + slot] = s;
    }
}

// ---------------- streaming fp32 -> bf16 hi/lo convert ----------------
// grid (NELEM/1024, 3); thread handles one float4.
__global__ __launch_bounds__(256) void convert_kernel(
    const float* __restrict__ Q, const float* __restrict__ K, const float* __restrict__ V)
{
    int tid = blockIdx.x*256 + threadIdx.x;              // float4 index
    int which = blockIdx.y;
    const float4* s = (const float4*)(which == 0 ? Q : (which == 1 ? K : V));
    uint2* dh = (uint2*)(which == 0 ? gQh : (which == 1 ? gKh : gVh));
    uint2* dl = (uint2*)(which == 0 ? gQl : (which == 1 ? gKl : gVl));
    float4 v = s[tid];
    uint2 uh, ul;
    split2(v.x, v.y, uh.x, ul.x);
    split2(v.z, v.w, uh.y, ul.y);
    dh[tid] = uh;
    dl[tid] = ul;
}

// ---------------- HMMA flash attention (gather inside, via cp.async) ----------------
// smem (bytes): Qh[128][136]bf16=34816, Ql=34816, 2 KV buffers of
// {Kh,Kl,Vh,Vl} 64x136 bf16 = 17408 each -> 69632/buffer; idx arrays 8192.
#define QSTR   272
#define OQH    0
#define OQL    34816
#define OKV    69632
#define KVBUF  69632
#define OFF_KH 0
#define OFF_KL 17408
#define OFF_VH 34816
#define OFF_VL 52224
#define OIDX0  208896
#define OIDX1  (208896 + 4096)
#define ASMEM  (208896 + 8192)

__global__ __launch_bounds__(256, 1) void attn_kernel(float* __restrict__ out) {
    int tile = blockIdx.x, h = blockIdx.y, b = blockIdx.z;
    int g = h >> 2;
    int cnt = g_cnt[b*2 + g];
    if (tile*128 >= cnt) return;

    extern __shared__ char sm[];
    uint32_t sb = smem_u32(sm);
    int t = threadIdx.x, lane = t & 31, w = t >> 5;
    int* si0 = (int*)(sm + OIDX0);
    int* si1 = (int*)(sm + OIDX1);

    // stage pair indices for this batch into smem (one pass)
    {
        const int* p0 = g_i0 + b*SEQ;
        const int* p1 = g_i1 + b*SEQ;
        #pragma unroll
        for (int i = 0; i < 4; i++) {
            si0[t + i*256] = p0[t + i*256];
            si1[t + i*256] = p1[t + i*256];
        }
    }
    __syncthreads();

    const size_t rowbase = (size_t)(b*HEADS + h) * SEQ;   // row index base (128 B rows)
    const int* listp = g_list + (b*2+g)*SEQ;

    // ---- Q tile gather: thread = one (row, half); 8+8 cp16 ----
    {
        int row = t >> 1, half = t & 1;
        int idx = tile*128 + row; if (idx >= cnt) idx = cnt - 1;
        int q = listp[idx];
        int src = half ? si1[q] : si0[q];
        size_t go = (rowbase + src) * 128;
        uint32_t dq = sb + (half ? 128u : 0u) + (uint32_t)row*QSTR;
        #pragma unroll
        for (int j = 0; j < 8; j++) {
            CP16(dq + OQH + j*16, gQh + go + j*16);
            CP16(dq + OQL + j*16, gQl + go + j*16);
        }
    }

    // ---- K/V tile gather issuer ----
    auto issue = [&](int kt, int buf) {
        int key = t >> 2, half = (t >> 1) & 1, c = t & 1;
        int k = kt*64 + key;
        int src = half ? si1[k] : si0[k];
        size_t go = (rowbase + src) * 128 + c*64;
        uint32_t base = sb + OKV + buf*KVBUF + (uint32_t)key*QSTR + half*128 + c*64;
        #pragma unroll
        for (int j = 0; j < 4; j++) {
            CP16(base + OFF_KH + j*16, gKh + go + j*16);
            CP16(base + OFF_KL + j*16, gKl + go + j*16);
            CP16(base + OFF_VH + j*16, gVh + go + j*16);
            CP16(base + OFF_VL + j*16, gVl + go + j*16);
        }
    };

    issue(0, 0);
    CP_COMMIT();

    // per-lane ldmatrix offsets
    int l15 = lane & 15;
    uint32_t aH = sb + OQH + (w*16 + l15)*QSTR + ((lane >> 4) * 8) * 2;
    uint32_t aL = sb + OQL + (w*16 + l15)*QSTR + ((lane >> 4) * 8) * 2;
    uint32_t bOff = (l15 & 7)*QSTR + ((l15 >> 3) * 8) * 2;   // K rows
    uint32_t vOff = l15*QSTR;                                 // V rows (trans)

    float st[32], ot[64];
    #pragma unroll
    for (int i = 0; i < 64; i++) ot[i] = 0.f;
    float mref0 = 0.f, mref1 = 0.f, lr0 = 0.f, lr1 = 0.f;
    int buf = 0;

    for (int kt = 0; kt < 16; kt++) {
        if (kt < 15) { issue(kt+1, buf ^ 1); CP_COMMIT(); CP_WAIT(1); }
        else         { CP_WAIT(0); }
        __syncthreads();

        uint32_t kbH = sb + OKV + buf*KVBUF + OFF_KH + bOff;
        uint32_t kbL = sb + OKV + buf*KVBUF + OFF_KL + bOff;
        uint32_t vbH = sb + OKV + buf*KVBUF + OFF_VH + vOff;
        uint32_t vbL = sb + OKV + buf*KVBUF + OFF_VL + vOff;

        // ---- QK: S = QhKh + QhKl + QlKh ----
        #pragma unroll
        for (int i = 0; i < 32; i++) st[i] = 0.f;
        #pragma unroll
        for (int ks = 0; ks < 8; ks++) {
            uint32_t ah[4], al[4];
            ldsm_x4(ah, aH + ks*32);
            ldsm_x4(al, aL + ks*32);
            #pragma unroll
            for (int nt = 0; nt < 8; nt++) {
                uint32_t bh[2], bl[2];
                ldsm_x2(bh, kbH + nt*8*QSTR + ks*32);
                ldsm_x2(bl, kbL + nt*8*QSTR + ks*32);
                mma16816(st + nt*4, ah, bh);
                mma16816(st + nt*4, ah, bl);
                mma16816(st + nt*4, al, bh);
            }
        }

        // ---- softmax (fixed reference from tile 0) ----
        if (kt == 0) {
            float m0 = -CUDART_INF_F, m1 = -CUDART_INF_F;
            #pragma unroll
            for (int nt = 0; nt < 8; nt++) {
                m0 = fmaxf(m0, fmaxf(st[nt*4],   st[nt*4+1]));
                m1 = fmaxf(m1, fmaxf(st[nt*4+2], st[nt*4+3]));
            }
            m0 = fmaxf(m0, __shfl_xor_sync(0xffffffffu, m0, 1));
            m0 = fmaxf(m0, __shfl_xor_sync(0xffffffffu, m0, 2));
            m1 = fmaxf(m1, __shfl_xor_sync(0xffffffffu, m1, 1));
            m1 = fmaxf(m1, __shfl_xor_sync(0xffffffffu, m1, 2));
            mref0 = m0; mref1 = m1;
        }
        uint32_t pph0[8], pph1[8], ppl0[8], ppl1[8];
        #pragma unroll
        for (int nt = 0; nt < 8; nt++) {
            float p00 = __expf(st[nt*4]   - mref0);
            float p01 = __expf(st[nt*4+1] - mref0);
            float p10 = __expf(st[nt*4+2] - mref1);
            float p11 = __expf(st[nt*4+3] - mref1);
            lr0 += p00 + p01;
            lr1 += p10 + p11;
            split2(p00, p01, pph0[nt], ppl0[nt]);
            split2(p10, p11, pph1[nt], ppl1[nt]);
        }

        // ---- PV: O += PhVh + PhVl + PlVh ----
        #pragma unroll
        for (int tt = 0; tt < 4; tt++) {
            uint32_t aPh[4] = { pph0[2*tt], pph1[2*tt], pph0[2*tt+1], pph1[2*tt+1] };
            uint32_t aPl[4] = { ppl0[2*tt], ppl1[2*tt], ppl0[2*tt+1], ppl1[2*tt+1] };
            #pragma unroll
            for (int nt = 0; nt < 16; nt++) {
                uint32_t vh[2], vl[2];
                ldsm_x2t(vh, vbH + tt*16*QSTR + nt*16);
                ldsm_x2t(vl, vbL + tt*16*QSTR + nt*16);
                mma16816(ot + nt*4, aPh, vh);
                mma16816(ot + nt*4, aPh, vl);
                mma16816(ot + nt*4, aPl, vh);
            }
        }
        __syncthreads();
        buf ^= 1;
    }

    // ---- epilogue ----
    lr0 += __shfl_xor_sync(0xffffffffu, lr0, 1);
    lr0 += __shfl_xor_sync(0xffffffffu, lr0, 2);
    lr1 += __shfl_xor_sync(0xffffffffu, lr1, 1);
    lr1 += __shfl_xor_sync(0xffffffffu, lr1, 2);
    float inv0 = 0.08838834764831845f / lr0;   // 1/sqrt(2D)
    float inv1 = 0.08838834764831845f / lr1;

    int r0 = tile*128 + w*16 + (lane >> 2);
    int colb = (lane & 3) * 2;
    if (r0 < cnt) {
        int q = listp[r0];
        float* op = out + ((size_t)(b*SEQ + q))*512 + (h & 3)*128;
        #pragma unroll
        for (int nt = 0; nt < 16; nt++)
            *(float2*)(op + nt*8 + colb) = make_float2(ot[nt*4]*inv0, ot[nt*4+1]*inv0);
    }
    int r1 = r0 + 8;
    if (r1 < cnt) {
        int q = listp[r1];
        float* op = out + ((size_t)(b*SEQ + q))*512 + (h & 3)*128;
        #pragma unroll
        for (int nt = 0; nt < 16; nt++)
            *(float2*)(op + nt*8 + colb) = make_float2(ot[nt*4+2]*inv1, ot[nt*4+3]*inv1);
    }
}

// ---------------- launch ----------------
extern "C" void kernel_launch(void* const* d_in, const int* in_sizes, int n_in,
                              void* d_out, int out_size) {
    const float* Q = (const float*)d_in[0];
    const float* K = (const float*)d_in[1];
    const float* V = (const float*)d_in[2];
    const float* C = (const float*)d_in[3];
    float* out = (float*)d_out;

    cudaFuncSetAttribute(attn_kernel, cudaFuncAttributeMaxDynamicSharedMemorySize, ASMEM);

    init_kernel<<<1, 32>>>();
    pairs_kernel<<<BATCH*SEQ, 256>>>(C);
    convert_kernel<<<dim3(NELEM/1024, 3), 256>>>(Q, K, V);
    attn_kernel<<<dim3(8, HEADS, BATCH), 256, ASMEM>>>(out);
}